// round 4
// baseline (speedup 1.0000x reference)
#include <cuda_runtime.h>
#include <cstdint>
#include <math.h>

// Problem dims (fixed): B=8, N=4096, D=1024, M = B*N = 32768
#define DIM      1024
#define SEQ      4096
#define BATCH    8
#define MROWS    32768              // B*N
#define MDSZ     ((size_t)MROWS * DIM)

// GEMM tiling
#define BM 128
#define BN 128
#define BK 16
#define SPAD 132                    // 128 + 4 pad, keeps 16B alignment (132*4=528, 528%16==0)

// ---------------------------------------------------------------------------
// Scratch (device globals: allocation-free kernel_launch)
// ---------------------------------------------------------------------------
__device__ float g_xT[(size_t)DIM * MROWS];            // x transposed  [D][M]      134MB
__device__ float g_wt[(size_t)4 * DIM * DIM];          // 4 transposed weights       16MB
__device__ float g_buf[(size_t)4 * MROWS * DIM];       // slabs: vr, vi, key, query 536MB
__device__ float g_valT[(size_t)BATCH * DIM * SEQ];    // value transposed [b][d][n] 134MB
__device__ float g_attn[(size_t)BATCH * DIM * DIM];    // feature attn [b][d][e]      33MB
__device__ float g_part[2 * BATCH * 16 * DIM];         // norm partial sums
__device__ float g_inv[2 * BATCH * DIM];               // 1/(norm+1e-5): [which][b][e]

// ---------------------------------------------------------------------------
// f32x2 packed-FMA helpers (B300: FFMA-3reg is half rate; fma.rn.f32x2 is full)
// ---------------------------------------------------------------------------
__device__ __forceinline__ unsigned long long pack2(float lo, float hi) {
    unsigned long long r;
    asm("mov.b64 %0, {%1, %2};" : "=l"(r) : "f"(lo), "f"(hi));
    return r;
}
__device__ __forceinline__ void unpack2(unsigned long long v, float& lo, float& hi) {
    asm("mov.b64 {%0, %1}, %2;" : "=f"(lo), "=f"(hi) : "l"(v));
}
__device__ __forceinline__ void ffma2(unsigned long long& d, unsigned long long a,
                                      unsigned long long b) {
    asm("fma.rn.f32x2 %0, %1, %2, %0;" : "+l"(d) : "l"(a), "l"(b));
}
__device__ __forceinline__ void cp16(unsigned s, const float* g) {
    asm volatile("cp.async.cg.shared.global [%0], [%1], 16;" :: "r"(s), "l"(g));
}

// ---------------------------------------------------------------------------
// TN GEMM core: C[m0:m0+128, n0:n0+128] = sum_k A[k][m] * B[k][n]
// A: [kdim][lda] row-major (reduction along rows), B: [kdim][ldb].
// cp.async double-buffered smem, 8x8 per-thread micro-tile, f32x2 packed FMA.
// All dims assumed multiples of tile sizes (true for this problem).
// ---------------------------------------------------------------------------
#define ISSUE_TILE(bufi, aptr, bptr) do {                                          \
    cp16((unsigned)__cvta_generic_to_shared(&As[bufi][lrow][lcol]), (aptr));       \
    cp16((unsigned)__cvta_generic_to_shared(&As[bufi][lrow+8][lcol]),              \
         (aptr) + 8*(size_t)lda);                                                  \
    cp16((unsigned)__cvta_generic_to_shared(&Bs[bufi][lrow][lcol]), (bptr));       \
    cp16((unsigned)__cvta_generic_to_shared(&Bs[bufi][lrow+8][lcol]),              \
         (bptr) + 8*(size_t)ldb);                                                  \
    asm volatile("cp.async.commit_group;");                                        \
} while (0)

__device__ __forceinline__ void gemm_tn_core(
    const float* __restrict__ A, int lda,
    const float* __restrict__ B, int ldb,
    int m0, int n0, int kdim,
    float (*As)[BK][SPAD], float (*Bs)[BK][SPAD],
    unsigned long long (&acc)[8][4])
{
    const int tid  = threadIdx.x;
    const int tx4  = (tid & 15) << 2;   // column group within tile
    const int ty4  = (tid >> 4) << 2;   // row group within tile
    const int lrow = tid >> 5;          // loader: k-row 0..7 (+8 second pass)
    const int lcol = (tid & 31) << 2;   // loader: 4-float column chunk

#pragma unroll
    for (int i = 0; i < 8; ++i)
#pragma unroll
        for (int j = 0; j < 4; ++j) acc[i][j] = 0ull;

    const float* ga = A + (size_t)lrow * lda + (m0 + lcol);
    const float* gb = B + (size_t)lrow * ldb + (n0 + lcol);

    ISSUE_TILE(0, ga, gb);
    asm volatile("cp.async.wait_group 0;" ::: "memory");
    __syncthreads();

    const int nk = kdim / BK;
    for (int kt = 0; kt < nk; ++kt) {
        const int buf = kt & 1;
        if (kt + 1 < nk) {
            ga += (size_t)BK * lda;
            gb += (size_t)BK * ldb;
            ISSUE_TILE(buf ^ 1, ga, gb);
        }
        const float (*Ac)[SPAD] = As[buf];
        const float (*Bc)[SPAD] = Bs[buf];
#pragma unroll
        for (int kk = 0; kk < BK; ++kk) {
            float4 a0 = *(const float4*)&Ac[kk][ty4];
            float4 a1 = *(const float4*)&Ac[kk][ty4 + 64];
            ulonglong2 b0 = *(const ulonglong2*)&Bc[kk][tx4];
            ulonglong2 b1 = *(const ulonglong2*)&Bc[kk][tx4 + 64];
            unsigned long long a2[8];
            a2[0] = pack2(a0.x, a0.x); a2[1] = pack2(a0.y, a0.y);
            a2[2] = pack2(a0.z, a0.z); a2[3] = pack2(a0.w, a0.w);
            a2[4] = pack2(a1.x, a1.x); a2[5] = pack2(a1.y, a1.y);
            a2[6] = pack2(a1.z, a1.z); a2[7] = pack2(a1.w, a1.w);
#pragma unroll
            for (int i = 0; i < 8; ++i) {
                ffma2(acc[i][0], a2[i], b0.x);
                ffma2(acc[i][1], a2[i], b0.y);
                ffma2(acc[i][2], a2[i], b1.x);
                ffma2(acc[i][3], a2[i], b1.y);
            }
        }
        asm volatile("cp.async.wait_group 0;" ::: "memory");
        __syncthreads();
    }
}

// ---------------------------------------------------------------------------
// Transposes (make every GEMM TN-layout so cp.async needs no in-flight swizzle)
// ---------------------------------------------------------------------------
__global__ void k_transpose_x(const float* __restrict__ x) {
    __shared__ float t[32][33];
    const int m0 = blockIdx.x * 32, d0 = blockIdx.y * 32;
    const int tx = threadIdx.x, ty = threadIdx.y;
#pragma unroll
    for (int j = 0; j < 4; ++j)
        t[ty + 8 * j][tx] = x[(size_t)(m0 + ty + 8 * j) * DIM + d0 + tx];
    __syncthreads();
#pragma unroll
    for (int j = 0; j < 4; ++j)
        g_xT[(size_t)(d0 + ty + 8 * j) * MROWS + m0 + tx] = t[tx][ty + 8 * j];
}

__global__ void k_transpose_w(const float* __restrict__ w0, const float* __restrict__ w1,
                              const float* __restrict__ w2, const float* __restrict__ w3) {
    __shared__ float t[32][33];
    const int z = blockIdx.z;
    const float* W = (z == 0) ? w0 : (z == 1) ? w1 : (z == 2) ? w2 : w3;
    float* dst = g_wt + (size_t)z * DIM * DIM;
    const int e0 = blockIdx.x * 32, d0 = blockIdx.y * 32;
    const int tx = threadIdx.x, ty = threadIdx.y;
#pragma unroll
    for (int j = 0; j < 4; ++j)
        t[ty + 8 * j][tx] = W[(size_t)(e0 + ty + 8 * j) * DIM + d0 + tx];
    __syncthreads();
#pragma unroll
    for (int j = 0; j < 4; ++j)
        dst[(size_t)(d0 + ty + 8 * j) * DIM + e0 + tx] = t[tx][ty + 8 * j];
}

// ---------------------------------------------------------------------------
// Projection GEMM: slabs 0..3 = xW^T + b for (Wvr, Wvi, Wk, Wq)
// C[m][e] = sum_d xT[d][m] * WT_z[d][e]
// ---------------------------------------------------------------------------
__global__ void __launch_bounds__(256, 2)
k_proj(const float* __restrict__ bvr, const float* __restrict__ bvi,
       const float* __restrict__ bk,  const float* __restrict__ bq) {
    __shared__ __align__(16) float As[2][BK][SPAD];
    __shared__ __align__(16) float Bs[2][BK][SPAD];
    const int z  = blockIdx.z;
    const int m0 = blockIdx.y * BM;
    const int n0 = blockIdx.x * BN;
    unsigned long long acc[8][4];
    gemm_tn_core(g_xT, MROWS, g_wt + (size_t)z * DIM * DIM, DIM,
                 m0, n0, DIM, As, Bs, acc);

    const float* bias = (z == 0) ? bvr : (z == 1) ? bvi : (z == 2) ? bk : bq;
    float* dst = g_buf + (size_t)z * MDSZ;
    const int tx4 = (threadIdx.x & 15) << 2;
    const int ty4 = (threadIdx.x >> 4) << 2;
    const int e0  = n0 + tx4;
    const float4 bv0 = *(const float4*)&bias[e0];
    const float4 bv1 = *(const float4*)&bias[e0 + 64];
#pragma unroll
    for (int i = 0; i < 8; ++i) {
        const int row = m0 + ty4 + (i < 4 ? i : 60 + i);
        float c[8];
        unpack2(acc[i][0], c[0], c[1]); unpack2(acc[i][1], c[2], c[3]);
        unpack2(acc[i][2], c[4], c[5]); unpack2(acc[i][3], c[6], c[7]);
        float4 o0 = make_float4(c[0] + bv0.x, c[1] + bv0.y, c[2] + bv0.z, c[3] + bv0.w);
        float4 o1 = make_float4(c[4] + bv1.x, c[5] + bv1.y, c[6] + bv1.z, c[7] + bv1.w);
        *(float4*)&dst[(size_t)row * DIM + e0]      = o0;
        *(float4*)&dst[(size_t)row * DIM + e0 + 64] = o1;
    }
}

// ---------------------------------------------------------------------------
// GLU gate + transpose: valueT[b][d][n] = vr * tanh(softplus(vi))
// ---------------------------------------------------------------------------
__device__ __forceinline__ float glu_gate(float vi) {
    const float sp = fmaxf(vi, 0.0f) + log1pf(expf(-fabsf(vi)));
    return tanhf(sp);
}

__global__ void k_glu_t() {
    __shared__ float t[32][33];
    const int b  = blockIdx.z;
    const int n0 = blockIdx.x * 32, d0 = blockIdx.y * 32;
    const int tx = threadIdx.x, ty = threadIdx.y;
    const float* vr = g_buf + (size_t)b * SEQ * DIM;
    const float* vi = g_buf + MDSZ + (size_t)b * SEQ * DIM;
#pragma unroll
    for (int j = 0; j < 4; ++j) {
        const size_t off = (size_t)(n0 + ty + 8 * j) * DIM + d0 + tx;
        t[ty + 8 * j][tx] = vr[off] * glu_gate(vi[off]);
    }
    __syncthreads();
    float* dst = g_valT + (size_t)b * DIM * SEQ;
#pragma unroll
    for (int j = 0; j < 4; ++j)
        dst[(size_t)(d0 + ty + 8 * j) * SEQ + n0 + tx] = t[tx][ty + 8 * j];
}

// ---------------------------------------------------------------------------
// Column L2 norms over the sequence dim for key (which=0) / query (which=1).
// Deterministic two-stage reduction (no float atomics).
// ---------------------------------------------------------------------------
__global__ void k_norm_partial() {
    const int which = blockIdx.z & 1;
    const int b     = blockIdx.z >> 1;
    const float* src = g_buf + (size_t)(2 + which) * MDSZ + (size_t)b * SEQ * DIM;
    const int col = blockIdx.x * 256 + threadIdx.x;
    const int n0  = blockIdx.y * 256;
    float s = 0.0f;
#pragma unroll 4
    for (int r = 0; r < 256; ++r) {
        const float v = src[(size_t)(n0 + r) * DIM + col];
        s += v * v;
    }
    g_part[(((size_t)which * BATCH + b) * 16 + blockIdx.y) * DIM + col] = s;
}

__global__ void k_norm_final() {
    const int idx = blockIdx.x * 256 + threadIdx.x;   // 0..16383
    const int col = idx & (DIM - 1);
    const int bw  = idx >> 10;                        // which*8 + b
    float s = 0.0f;
#pragma unroll
    for (int c = 0; c < 16; ++c)
        s += g_part[((size_t)bw * 16 + c) * DIM + col];
    g_inv[idx] = 1.0f / (sqrtf(s) + 1e-5f);
}

// ---------------------------------------------------------------------------
// Feature attention: attn[b][d][e] = smu( (K^T Q)[d][e] * invk[d] * invq[e] )
// smu with MU=1e6, alpha=0.25:  y = v*(0.625 + 0.375*erf(750000*v))
// ---------------------------------------------------------------------------
__global__ void __launch_bounds__(256, 2)
k_attn() {
    __shared__ __align__(16) float As[2][BK][SPAD];
    __shared__ __align__(16) float Bs[2][BK][SPAD];
    const int b  = blockIdx.z;
    const int m0 = blockIdx.y * BM;   // d
    const int n0 = blockIdx.x * BN;   // e
    unsigned long long acc[8][4];
    const float* Kp = g_buf + (size_t)2 * MDSZ + (size_t)b * SEQ * DIM;
    const float* Qp = g_buf + (size_t)3 * MDSZ + (size_t)b * SEQ * DIM;
    gemm_tn_core(Kp, DIM, Qp, DIM, m0, n0, SEQ, As, Bs, acc);

    const float* invk = g_inv + b * DIM;
    const float* invq = g_inv + BATCH * DIM + b * DIM;
    const int tx4 = (threadIdx.x & 15) << 2;
    const int ty4 = (threadIdx.x >> 4) << 2;
    const int e0  = n0 + tx4;
    const float4 q0 = *(const float4*)&invq[e0];
    const float4 q1 = *(const float4*)&invq[e0 + 64];
    const float qv[8] = {q0.x, q0.y, q0.z, q0.w, q1.x, q1.y, q1.z, q1.w};
    float* dst = g_attn + (size_t)b * DIM * DIM;
#pragma unroll
    for (int i = 0; i < 8; ++i) {
        const int d = m0 + ty4 + (i < 4 ? i : 60 + i);
        const float ik = invk[d];
        float c[8];
        unpack2(acc[i][0], c[0], c[1]); unpack2(acc[i][1], c[2], c[3]);
        unpack2(acc[i][2], c[4], c[5]); unpack2(acc[i][3], c[6], c[7]);
#pragma unroll
        for (int j = 0; j < 8; ++j) {
            const float v = c[j] * ik * qv[j];
            c[j] = v * (0.625f + 0.375f * erff(750000.0f * v));
        }
        *(float4*)&dst[(size_t)d * DIM + e0]      = make_float4(c[0], c[1], c[2], c[3]);
        *(float4*)&dst[(size_t)d * DIM + e0 + 64] = make_float4(c[4], c[5], c[6], c[7]);
    }
}

// ---------------------------------------------------------------------------
// Output: out[b][n][e] = sum_d valueT[b][d][n] * attn[b][d][e]
// ---------------------------------------------------------------------------
__global__ void __launch_bounds__(256, 2)
k_out(float* __restrict__ out) {
    __shared__ __align__(16) float As[2][BK][SPAD];
    __shared__ __align__(16) float Bs[2][BK][SPAD];
    const int b  = blockIdx.z;
    const int m0 = blockIdx.y * BM;   // n
    const int n0 = blockIdx.x * BN;   // e
    unsigned long long acc[8][4];
    gemm_tn_core(g_valT + (size_t)b * DIM * SEQ, SEQ,
                 g_attn + (size_t)b * DIM * DIM, DIM,
                 m0, n0, DIM, As, Bs, acc);

    float* dst = out + (size_t)b * SEQ * DIM;
    const int tx4 = (threadIdx.x & 15) << 2;
    const int ty4 = (threadIdx.x >> 4) << 2;
    const int e0  = n0 + tx4;
#pragma unroll
    for (int i = 0; i < 8; ++i) {
        const int row = m0 + ty4 + (i < 4 ? i : 60 + i);
        float c[8];
        unpack2(acc[i][0], c[0], c[1]); unpack2(acc[i][1], c[2], c[3]);
        unpack2(acc[i][2], c[4], c[5]); unpack2(acc[i][3], c[6], c[7]);
        *(float4*)&dst[(size_t)row * DIM + e0]      = make_float4(c[0], c[1], c[2], c[3]);
        *(float4*)&dst[(size_t)row * DIM + e0 + 64] = make_float4(c[4], c[5], c[6], c[7]);
    }
}

// ---------------------------------------------------------------------------
// Launch: pure kernel launches, graph-capturable, allocation-free.
// Input order (metadata): x, Wvr, bvr, Wvi, bvi, Wk, bk, Wq, bq
// ---------------------------------------------------------------------------
extern "C" void kernel_launch(void* const* d_in, const int* in_sizes, int n_in,
                              void* d_out, int out_size) {
    const float* x   = (const float*)d_in[0];
    const float* Wvr = (const float*)d_in[1];
    const float* bvr = (const float*)d_in[2];
    const float* Wvi = (const float*)d_in[3];
    const float* bvi = (const float*)d_in[4];
    const float* Wk  = (const float*)d_in[5];
    const float* bk  = (const float*)d_in[6];
    const float* Wq  = (const float*)d_in[7];
    const float* bq  = (const float*)d_in[8];
    float* out = (float*)d_out;

    k_transpose_x<<<dim3(MROWS / 32, DIM / 32), dim3(32, 8)>>>(x);
    k_transpose_w<<<dim3(DIM / 32, DIM / 32, 4), dim3(32, 8)>>>(Wvr, Wvi, Wk, Wq);
    k_proj<<<dim3(DIM / BN, MROWS / BM, 4), 256>>>(bvr, bvi, bk, bq);
    k_glu_t<<<dim3(SEQ / 32, DIM / 32, BATCH), dim3(32, 8)>>>();
    k_norm_partial<<<dim3(DIM / 256, 16, 2 * BATCH), 256>>>();
    k_norm_final<<<(2 * BATCH * DIM) / 256, 256>>>();
    k_attn<<<dim3(DIM / BN, DIM / BM, BATCH), 256>>>();
    k_out<<<dim3(DIM / BN, SEQ / BM, BATCH), 256>>>(out);
}

// round 12
// speedup vs baseline: 2.2064x; 2.2064x over previous
#include <cuda_runtime.h>
#include <cuda_bf16.h>
#include <cstdint>
#include <math.h>

// Problem dims (fixed): B=8, N=4096, D=1024
#define DIM    1024
#define SEQ    4096
#define BATCH  8
#define MROWS  32768                       // B*N
#define MDSZ   ((size_t)MROWS * DIM)

// CTA tile 128x128, K-chunk 64 bf16 (=128B rows, SW128-style swizzle)
#define TM   128
#define TN   128
#define TK   64
#define ROWB 128                           // bytes per smem row (64 bf16)
#define SLAB (128 * ROWB)                  // 16 KB: one operand tile
#define OFF_AHI 0
#define OFF_ALO (SLAB)
#define OFF_BHI (2 * SLAB)
#define OFF_BLO (3 * SLAB)
#define STAGE   (4 * SLAB)                 // 64 KB
#define SMEM_BYTES (2 * STAGE)             // 128 KB

// ---------------------------------------------------------------------------
// Scratch (device globals: allocation-free kernel_launch)
// ---------------------------------------------------------------------------
__device__ __nv_bfloat16 g_xhi[MDSZ], g_xlo[MDSZ];                 // x split
__device__ __nv_bfloat16 g_whi[(size_t)4*DIM*DIM], g_wlo[(size_t)4*DIM*DIM];
__device__ float         g_buf[(size_t)4*MROWS*DIM];               // vr,vi,k,q
__device__ __nv_bfloat16 g_vhi[MDSZ], g_vlo[MDSZ];                 // value split
__device__ __nv_bfloat16 g_kthi[(size_t)BATCH*DIM*SEQ], g_ktlo[(size_t)BATCH*DIM*SEQ];
__device__ __nv_bfloat16 g_qthi[(size_t)BATCH*DIM*SEQ], g_qtlo[(size_t)BATCH*DIM*SEQ];
__device__ __nv_bfloat16 g_athi[(size_t)BATCH*DIM*DIM], g_atlo[(size_t)BATCH*DIM*DIM];
__device__ float g_part[2 * BATCH * 16 * DIM];
__device__ float g_inv[2 * BATCH * DIM];

// ---------------------------------------------------------------------------
// Family-safe PTX helpers (sm_80+ ISA only: cp.async / ldmatrix / mma.sync)
// ---------------------------------------------------------------------------
__device__ __forceinline__ void cp16(uint32_t s, const void* g) {
    asm volatile("cp.async.cg.shared.global [%0], [%1], 16;" :: "r"(s), "l"(g));
}
__device__ __forceinline__ void ldsm4(uint32_t (&r)[4], uint32_t a) {
    asm volatile("ldmatrix.sync.aligned.m8n8.x4.shared.b16 {%0,%1,%2,%3}, [%4];"
                 : "=r"(r[0]), "=r"(r[1]), "=r"(r[2]), "=r"(r[3]) : "r"(a));
}
__device__ __forceinline__ void mma16816(float (&d)[4], const uint32_t (&a)[4],
                                         const uint32_t* b) {
    asm volatile(
        "mma.sync.aligned.m16n8k16.row.col.f32.bf16.bf16.f32 "
        "{%0,%1,%2,%3}, {%4,%5,%6,%7}, {%8,%9}, {%0,%1,%2,%3};"
        : "+f"(d[0]), "+f"(d[1]), "+f"(d[2]), "+f"(d[3])
        : "r"(a[0]), "r"(a[1]), "r"(a[2]), "r"(a[3]), "r"(b[0]), "r"(b[1]));
}

// ---------------------------------------------------------------------------
// Stage loader: 4 slabs (A hi/lo, B hi/lo), each 128 rows x 128B, swizzled.
// 256 threads x 16 cp.async each. Swizzle: 16B chunk c at row r -> c ^ (r&7).
// ---------------------------------------------------------------------------
__device__ __forceinline__ void load_stage(
    uint32_t sb,
    const __nv_bfloat16* __restrict__ Ahi, const __nv_bfloat16* __restrict__ Alo,
    int lda, int m0,
    const __nv_bfloat16* __restrict__ Bhi, const __nv_bfloat16* __restrict__ Blo,
    int ldb, int n0, int k0, int tid)
{
    const uint32_t cb = (uint32_t)(tid & 7) * 16;
    const int rb = tid >> 3;                 // 0..31
#pragma unroll
    for (int rr = 0; rr < 4; ++rr) {
        const int row = rb + rr * 32;
        const uint32_t sw = (uint32_t)row * ROWB + (cb ^ ((uint32_t)(row & 7) << 4));
        const char* pah = (const char*)(Ahi + (size_t)(m0 + row) * lda + k0) + cb;
        const char* pal = (const char*)(Alo + (size_t)(m0 + row) * lda + k0) + cb;
        const char* pbh = (const char*)(Bhi + (size_t)(n0 + row) * ldb + k0) + cb;
        const char* pbl = (const char*)(Blo + (size_t)(n0 + row) * ldb + k0) + cb;
        cp16(sb + OFF_AHI + sw, pah);
        cp16(sb + OFF_ALO + sw, pal);
        cp16(sb + OFF_BHI + sw, pbh);
        cp16(sb + OFF_BLO + sw, pbl);
    }
    asm volatile("cp.async.commit_group;" ::: "memory");
}

// ---------------------------------------------------------------------------
// Per-stage compute: warp tile 64x32, 4 k16 steps, 3 products (hh, hl, lh).
// Product-pass-outermost ordering: each acc reg is revisited every 16 MMAs.
// ---------------------------------------------------------------------------
__device__ __forceinline__ void compute_stage(uint32_t sb, int lane, int wm, int wn,
                                              float (&acc)[4][4][4])
{
#pragma unroll
    for (int kk = 0; kk < 4; ++kk) {
        uint32_t ah[4][4], al[4][4];
#pragma unroll
        for (int im = 0; im < 4; ++im) {
            const int row = wm * 64 + im * 16 + (lane & 15);
            const uint32_t c = (uint32_t)(kk * 2 + (lane >> 4));
            const uint32_t a = sb + OFF_AHI + (uint32_t)row * ROWB
                             + ((c ^ (uint32_t)(row & 7)) << 4);
            ldsm4(ah[im], a);
            ldsm4(al[im], a + (OFF_ALO - OFF_AHI));
        }
        uint32_t bh[2][4], bl[2][4];
#pragma unroll
        for (int in2 = 0; in2 < 2; ++in2) {
            const int row = wn * 32 + in2 * 16 + ((lane >> 4) << 3) + (lane & 7);
            const uint32_t c = (uint32_t)(kk * 2 + ((lane >> 3) & 1));
            const uint32_t a = sb + OFF_BHI + (uint32_t)row * ROWB
                             + ((c ^ (uint32_t)(row & 7)) << 4);
            ldsm4(bh[in2], a);
            ldsm4(bl[in2], a + (OFF_BLO - OFF_BHI));
        }
#pragma unroll
        for (int im = 0; im < 4; ++im)
#pragma unroll
            for (int jn = 0; jn < 4; ++jn)
                mma16816(acc[im][jn], ah[im], &bh[jn >> 1][(jn & 1) * 2]);
#pragma unroll
        for (int im = 0; im < 4; ++im)
#pragma unroll
            for (int jn = 0; jn < 4; ++jn)
                mma16816(acc[im][jn], ah[im], &bl[jn >> 1][(jn & 1) * 2]);
#pragma unroll
        for (int im = 0; im < 4; ++im)
#pragma unroll
            for (int jn = 0; jn < 4; ++jn)
                mma16816(acc[im][jn], al[im], &bh[jn >> 1][(jn & 1) * 2]);
    }
}

// ---------------------------------------------------------------------------
// Full mainloop: D[m][n] = sum_k (Ahi+Alo)[m][k] * (Bhi+Blo)[n][k]  (3 products)
// ---------------------------------------------------------------------------
__device__ __forceinline__ void gemm_mainloop(
    char* smem,
    const __nv_bfloat16* Ahi, const __nv_bfloat16* Alo, int lda, int m0,
    const __nv_bfloat16* Bhi, const __nv_bfloat16* Blo, int ldb, int n0,
    int nk, float (&acc)[4][4][4])
{
    const int tid  = threadIdx.x;
    const int lane = tid & 31, wid = tid >> 5;
    const int wm = wid >> 2, wn = wid & 3;
    const uint32_t sb = (uint32_t)__cvta_generic_to_shared(smem);

#pragma unroll
    for (int i = 0; i < 4; ++i)
#pragma unroll
        for (int j = 0; j < 4; ++j)
#pragma unroll
            for (int q = 0; q < 4; ++q) acc[i][j][q] = 0.0f;

    load_stage(sb, Ahi, Alo, lda, m0, Bhi, Blo, ldb, n0, 0, tid);

    for (int kt = 0; kt < nk; ++kt) {
        asm volatile("cp.async.wait_group 0;" ::: "memory");
        __syncthreads();
        if (kt + 1 < nk)
            load_stage(sb + (uint32_t)(((kt + 1) & 1)) * STAGE, Ahi, Alo, lda, m0,
                       Bhi, Blo, ldb, n0, (kt + 1) * TK, tid);
        compute_stage(sb + (uint32_t)(kt & 1) * STAGE, lane, wm, wn, acc);
        __syncthreads();
    }
}

// ---------------------------------------------------------------------------
// Elementwise: fp32 -> (bf16 hi, bf16 lo) splits
// ---------------------------------------------------------------------------
__device__ __forceinline__ void split1(float v, __nv_bfloat16& h, __nv_bfloat16& l) {
    h = __float2bfloat16_rn(v);
    l = __float2bfloat16_rn(v - __bfloat162float(h));
}

__global__ void k_split2(const float* __restrict__ in,
                         __nv_bfloat16* __restrict__ hi,
                         __nv_bfloat16* __restrict__ lo) {
    const size_t i = (size_t)blockIdx.x * blockDim.x + threadIdx.x;
    const float4 v = ((const float4*)in)[i];
    __nv_bfloat16 h0, h1, h2, h3, l0, l1, l2, l3;
    split1(v.x, h0, l0); split1(v.y, h1, l1);
    split1(v.z, h2, l2); split1(v.w, h3, l3);
    ((__nv_bfloat162*)hi)[2 * i]     = __halves2bfloat162(h0, h1);
    ((__nv_bfloat162*)hi)[2 * i + 1] = __halves2bfloat162(h2, h3);
    ((__nv_bfloat162*)lo)[2 * i]     = __halves2bfloat162(l0, l1);
    ((__nv_bfloat162*)lo)[2 * i + 1] = __halves2bfloat162(l2, l3);
}

__device__ __forceinline__ float glu_gate(float vi) {
    const float sp = fmaxf(vi, 0.0f) + log1pf(expf(-fabsf(vi)));
    return tanhf(sp);
}

__global__ void k_glu_split() {
    const size_t i = (size_t)blockIdx.x * blockDim.x + threadIdx.x;
    const float4 vr = ((const float4*)g_buf)[i];
    const float4 vi = ((const float4*)(g_buf + MDSZ))[i];
    float4 v;
    v.x = vr.x * glu_gate(vi.x); v.y = vr.y * glu_gate(vi.y);
    v.z = vr.z * glu_gate(vi.z); v.w = vr.w * glu_gate(vi.w);
    __nv_bfloat16 h0, h1, h2, h3, l0, l1, l2, l3;
    split1(v.x, h0, l0); split1(v.y, h1, l1);
    split1(v.z, h2, l2); split1(v.w, h3, l3);
    ((__nv_bfloat162*)g_vhi)[2 * i]     = __halves2bfloat162(h0, h1);
    ((__nv_bfloat162*)g_vhi)[2 * i + 1] = __halves2bfloat162(h2, h3);
    ((__nv_bfloat162*)g_vlo)[2 * i]     = __halves2bfloat162(l0, l1);
    ((__nv_bfloat162*)g_vlo)[2 * i + 1] = __halves2bfloat162(l2, l3);
}

// key/query: fp32 [b][n][d] -> transposed bf16 hi/lo [b][d][n]
__global__ void k_t_split() {
    __shared__ float t[32][33];
    const int which = blockIdx.z >> 3;     // 0=key, 1=query
    const int b     = blockIdx.z & 7;
    const float* src = g_buf + (size_t)(2 + which) * MDSZ + (size_t)b * SEQ * DIM;
    __nv_bfloat16* dh = (which ? g_qthi : g_kthi) + (size_t)b * DIM * SEQ;
    __nv_bfloat16* dl = (which ? g_qtlo : g_ktlo) + (size_t)b * DIM * SEQ;
    const int n0 = blockIdx.x * 32, d0 = blockIdx.y * 32;
    const int tx = threadIdx.x, ty = threadIdx.y;
#pragma unroll
    for (int j = 0; j < 4; ++j)
        t[ty + 8 * j][tx] = src[(size_t)(n0 + ty + 8 * j) * DIM + d0 + tx];
    __syncthreads();
#pragma unroll
    for (int j = 0; j < 4; ++j) {
        const float v = t[tx][ty + 8 * j];
        __nv_bfloat16 h, l;
        split1(v, h, l);
        const size_t off = (size_t)(d0 + ty + 8 * j) * SEQ + n0 + tx;
        dh[off] = h; dl[off] = l;
    }
}

// Column L2 norms over sequence dim (deterministic two-stage)
__global__ void k_norm_partial() {
    const int which = blockIdx.z & 1;
    const int b     = blockIdx.z >> 1;
    const float* src = g_buf + (size_t)(2 + which) * MDSZ + (size_t)b * SEQ * DIM;
    const int col = blockIdx.x * 256 + threadIdx.x;
    const int n0  = blockIdx.y * 256;
    float s = 0.0f;
#pragma unroll 4
    for (int r = 0; r < 256; ++r) {
        const float v = src[(size_t)(n0 + r) * DIM + col];
        s += v * v;
    }
    g_part[(((size_t)which * BATCH + b) * 16 + blockIdx.y) * DIM + col] = s;
}

__global__ void k_norm_final() {
    const int idx = blockIdx.x * 256 + threadIdx.x;
    const int bw  = idx >> 10;
    const int col = idx & (DIM - 1);
    float s = 0.0f;
#pragma unroll
    for (int c = 0; c < 16; ++c)
        s += g_part[((size_t)bw * 16 + c) * DIM + col];
    g_inv[idx] = 1.0f / (sqrtf(s) + 1e-5f);
}

// ---------------------------------------------------------------------------
// MMA kernels (epilogue uses the m16n8 C layout: rows lane>>2 / +8,
// cols (lane&3)*2 + {0,1})
// ---------------------------------------------------------------------------
__global__ void __launch_bounds__(256, 1)
k_proj_mma(const float* __restrict__ b0, const float* __restrict__ b1,
           const float* __restrict__ b2, const float* __restrict__ b3) {
    extern __shared__ char smem[];
    const int z  = blockIdx.z;
    const int m0 = blockIdx.y * TM;
    const int n0 = blockIdx.x * TN;
    float acc[4][4][4];
    gemm_mainloop(smem, g_xhi, g_xlo, DIM, m0,
                  g_whi + (size_t)z * DIM * DIM, g_wlo + (size_t)z * DIM * DIM,
                  DIM, n0, DIM / TK, acc);

    const int lane = threadIdx.x & 31, wid = threadIdx.x >> 5;
    const int wm = wid >> 2, wn = wid & 3;
    const float* bias = ((z == 0) ? b0 : (z == 1) ? b1 : (z == 2) ? b2 : b3);
    float* dst = g_buf + (size_t)z * MDSZ;
    const int r0 = m0 + wm * 64 + (lane >> 2);
    const int c0 = n0 + wn * 32 + (lane & 3) * 2;
#pragma unroll
    for (int im = 0; im < 4; ++im)
#pragma unroll
        for (int jn = 0; jn < 4; ++jn) {
            const int r = r0 + im * 16, c = c0 + jn * 8;
            const float2 bv = *(const float2*)&bias[c];
            float2 o0 = make_float2(acc[im][jn][0] + bv.x, acc[im][jn][1] + bv.y);
            float2 o1 = make_float2(acc[im][jn][2] + bv.x, acc[im][jn][3] + bv.y);
            *(float2*)&dst[(size_t)r * DIM + c]       = o0;
            *(float2*)&dst[(size_t)(r + 8) * DIM + c] = o1;
        }
}

// attn^T[e][d] = smu( (sum_n Q[n][e] K[n][d]) * iq[e] * ik[d] ), split to bf16
__global__ void __launch_bounds__(256, 1)
k_attn_mma() {
    extern __shared__ char smem[];
    const int b  = blockIdx.z;
    const int m0 = blockIdx.y * TM;   // e
    const int n0 = blockIdx.x * TN;   // d
    float acc[4][4][4];
    gemm_mainloop(smem,
        g_qthi + (size_t)b * DIM * SEQ, g_qtlo + (size_t)b * DIM * SEQ, SEQ, m0,
        g_kthi + (size_t)b * DIM * SEQ, g_ktlo + (size_t)b * DIM * SEQ, SEQ, n0,
        SEQ / TK, acc);

    const int lane = threadIdx.x & 31, wid = threadIdx.x >> 5;
    const int wm = wid >> 2, wn = wid & 3;
    const float* ikp = g_inv + b * DIM;
    const float* iqp = g_inv + BATCH * DIM + b * DIM;
    const int r0 = m0 + wm * 64 + (lane >> 2);
    const int c0 = n0 + wn * 32 + (lane & 3) * 2;
#pragma unroll
    for (int im = 0; im < 4; ++im)
#pragma unroll
        for (int jn = 0; jn < 4; ++jn) {
            const int e = r0 + im * 16, d = c0 + jn * 8;
            const float2 ik = *(const float2*)&ikp[d];
            const float iq0 = iqp[e], iq1 = iqp[e + 8];
            float v[4];
            v[0] = acc[im][jn][0] * iq0 * ik.x;
            v[1] = acc[im][jn][1] * iq0 * ik.y;
            v[2] = acc[im][jn][2] * iq1 * ik.x;
            v[3] = acc[im][jn][3] * iq1 * ik.y;
#pragma unroll
            for (int q = 0; q < 4; ++q)
                v[q] = v[q] * (0.625f + 0.375f * erff(750000.0f * v[q]));
            __nv_bfloat16 h[4], l[4];
#pragma unroll
            for (int q = 0; q < 4; ++q) split1(v[q], h[q], l[q]);
            const size_t o0 = ((size_t)b * DIM + e) * DIM + d;
            const size_t o1 = ((size_t)b * DIM + e + 8) * DIM + d;
            *(__nv_bfloat162*)&g_athi[o0] = __halves2bfloat162(h[0], h[1]);
            *(__nv_bfloat162*)&g_atlo[o0] = __halves2bfloat162(l[0], l[1]);
            *(__nv_bfloat162*)&g_athi[o1] = __halves2bfloat162(h[2], h[3]);
            *(__nv_bfloat162*)&g_atlo[o1] = __halves2bfloat162(l[2], l[3]);
        }
}

// out[b][n][e] = sum_d value[n][d] * attn^T[e][d]
__global__ void __launch_bounds__(256, 1)
k_out_mma(float* __restrict__ out) {
    extern __shared__ char smem[];
    const int b  = blockIdx.z;
    const int m0 = blockIdx.y * TM;   // n
    const int n0 = blockIdx.x * TN;   // e
    float acc[4][4][4];
    gemm_mainloop(smem,
        g_vhi + (size_t)b * SEQ * DIM, g_vlo + (size_t)b * SEQ * DIM, DIM, m0,
        g_athi + (size_t)b * DIM * DIM, g_atlo + (size_t)b * DIM * DIM, DIM, n0,
        DIM / TK, acc);

    const int lane = threadIdx.x & 31, wid = threadIdx.x >> 5;
    const int wm = wid >> 2, wn = wid & 3;
    float* dst = out + (size_t)b * SEQ * DIM;
    const int r0 = m0 + wm * 64 + (lane >> 2);
    const int c0 = n0 + wn * 32 + (lane & 3) * 2;
#pragma unroll
    for (int im = 0; im < 4; ++im)
#pragma unroll
        for (int jn = 0; jn < 4; ++jn) {
            const int r = r0 + im * 16, c = c0 + jn * 8;
            *(float2*)&dst[(size_t)r * DIM + c] =
                make_float2(acc[im][jn][0], acc[im][jn][1]);
            *(float2*)&dst[(size_t)(r + 8) * DIM + c] =
                make_float2(acc[im][jn][2], acc[im][jn][3]);
        }
}

// ---------------------------------------------------------------------------
// Launch (graph-capturable, allocation-free)
// Inputs: x, Wvr, bvr, Wvi, bvi, Wk, bk, Wq, bq
// ---------------------------------------------------------------------------
extern "C" void kernel_launch(void* const* d_in, const int* in_sizes, int n_in,
                              void* d_out, int out_size) {
    (void)in_sizes; (void)n_in; (void)out_size;
    const float* x   = (const float*)d_in[0];
    const float* Wvr = (const float*)d_in[1];
    const float* bvr = (const float*)d_in[2];
    const float* Wvi = (const float*)d_in[3];
    const float* bvi = (const float*)d_in[4];
    const float* Wk  = (const float*)d_in[5];
    const float* bk  = (const float*)d_in[6];
    const float* Wq  = (const float*)d_in[7];
    const float* bq  = (const float*)d_in[8];
    float* out = (float*)d_out;

    cudaFuncSetAttribute(k_proj_mma, cudaFuncAttributeMaxDynamicSharedMemorySize, SMEM_BYTES);
    cudaFuncSetAttribute(k_attn_mma, cudaFuncAttributeMaxDynamicSharedMemorySize, SMEM_BYTES);
    cudaFuncSetAttribute(k_out_mma,  cudaFuncAttributeMaxDynamicSharedMemorySize, SMEM_BYTES);

    __nv_bfloat16 *whi, *wlo, *xhi, *xlo;
    cudaGetSymbolAddress((void**)&whi, g_whi);
    cudaGetSymbolAddress((void**)&wlo, g_wlo);
    cudaGetSymbolAddress((void**)&xhi, g_xhi);
    cudaGetSymbolAddress((void**)&xlo, g_xlo);

    const int WSZ = DIM * DIM;
    k_split2<<<(int)(MDSZ / 4 / 256), 256>>>(x, xhi, xlo);
    k_split2<<<WSZ / 4 / 256, 256>>>(Wvr, whi,           wlo);
    k_split2<<<WSZ / 4 / 256, 256>>>(Wvi, whi + WSZ,     wlo + WSZ);
    k_split2<<<WSZ / 4 / 256, 256>>>(Wk,  whi + 2 * WSZ, wlo + 2 * WSZ);
    k_split2<<<WSZ / 4 / 256, 256>>>(Wq,  whi + 3 * WSZ, wlo + 3 * WSZ);

    k_proj_mma<<<dim3(DIM / TN, MROWS / TM, 4), 256, SMEM_BYTES>>>(bvr, bvi, bk, bq);

    k_glu_split<<<(int)(MDSZ / 4 / 256), 256>>>();
    k_t_split<<<dim3(SEQ / 32, DIM / 32, 2 * BATCH), dim3(32, 8)>>>();
    k_norm_partial<<<dim3(DIM / 256, 16, 2 * BATCH), 256>>>();
    k_norm_final<<<(2 * BATCH * DIM) / 256, 256>>>();

    k_attn_mma<<<dim3(DIM / TN, DIM / TM, BATCH), 256, SMEM_BYTES>>>();
    k_out_mma<<<dim3(DIM / TN, SEQ / TM, BATCH), 256, SMEM_BYTES>>>(out);
}